// round 16
// baseline (speedup 1.0000x reference)
#include <cuda_runtime.h>

// Problem constants
#define BB 2
#define NN 512
#define FF 128
#define HH 256          // 2F
#define NEG_SLOPE 0.04f
#define MASK_VAL  (-9e15f)

#define BN (BB*NN)      // 1024 rows total

// Scratch: PB[bn][h] = p + b1 (row-major, h contiguous)
//          QT[h][bn] = q      (transposed: bn contiguous per h)
__device__ float g_PB[BN * HH];
__device__ float g_QT[HH * BN];

// ---------------------------------------------------------------------------
// Kernel 1: fused p/q projection.  256 blocks x 256 threads, 4 rows/block.
// ---------------------------------------------------------------------------
__global__ __launch_bounds__(256) void pq_kernel(
    const float* __restrict__ x,
    const float* __restrict__ w1,
    const float* __restrict__ b1)
{
    __shared__ float xs[4 * FF];          // 4 rows x 128
    const int tid = threadIdx.x;
    const int bn0 = blockIdx.x * 4;

    if (tid < 128)                         // 512 floats = 128 float4
        ((float4*)xs)[tid] = ((const float4*)(x + (size_t)bn0 * FF))[tid];
    __syncthreads();

    const int h = tid;
    const float* __restrict__ wrow = w1 + (size_t)h * (2 * FF);

    float accP[4] = {0.f, 0.f, 0.f, 0.f};
    float accQ[4] = {0.f, 0.f, 0.f, 0.f};

#pragma unroll 4
    for (int f = 0; f < FF; f += 4) {
        const float4 wp = *(const float4*)(wrow + f);
        const float4 wq = *(const float4*)(wrow + FF + f);
#pragma unroll
        for (int r = 0; r < 4; ++r) {
            const float x0 = xs[r * FF + f + 0];
            const float x1 = xs[r * FF + f + 1];
            const float x2 = xs[r * FF + f + 2];
            const float x3 = xs[r * FF + f + 3];
            accP[r] = fmaf(x0, wp.x, accP[r]);
            accP[r] = fmaf(x1, wp.y, accP[r]);
            accP[r] = fmaf(x2, wp.z, accP[r]);
            accP[r] = fmaf(x3, wp.w, accP[r]);
            accQ[r] = fmaf(x0, wq.x, accQ[r]);
            accQ[r] = fmaf(x1, wq.y, accQ[r]);
            accQ[r] = fmaf(x2, wq.z, accQ[r]);
            accQ[r] = fmaf(x3, wq.w, accQ[r]);
        }
    }

    const float b1h = b1[h];
#pragma unroll
    for (int r = 0; r < 4; ++r)
        g_PB[(size_t)(bn0 + r) * HH + h] = accP[r] + b1h;

    float4 qa = make_float4(accQ[0], accQ[1], accQ[2], accQ[3]);
    *(float4*)(g_QT + (size_t)h * BN + bn0) = qa;
}

// ---------------------------------------------------------------------------
// Kernel 2: e-scores + leaky + mask + softmax + att@x, fused.
// 128 blocks (b x 64 i-tiles of 8 rows), 512 threads.
// Thread tile: 4 consecutive j (jq = tid&127) x 2 rows (r0 = (tid>>7)*2).
// Q tile double-buffered (1 sync/chunk); q loaded to registers in a burst.
// ---------------------------------------------------------------------------
__global__ __launch_bounds__(512) void attn_kernel(
    const float* __restrict__ x,
    const float* __restrict__ w2,
    const float* __restrict__ b2,
    const int*   __restrict__ adj,
    float* __restrict__ out,
    int write_att)
{
    __shared__ float q_sm[2 * 8 * NN];   // 32 KB double buffer (later: att tile)
    __shared__ float a_sm[8 * HH];       // 8 KB : PB rows (later: AV partials)
    __shared__ float w2_sm[HH];          // 1 KB
    __shared__ float redm[8][4];         // per-row warp partial max
    __shared__ float reds[8][4];         // per-row warp partial sum

    const int tid = threadIdx.x;           // 0..511
    const int jq  = tid & 127;             // j quad: j = 4*jq+k
    const int rg  = tid >> 7;              // 0..3
    const int r0  = rg * 2;                // rows r0, r0+1
    const int b   = blockIdx.x >> 6;
    const int it0 = (blockIdx.x & 63) << 3;
    const int base = b * NN + it0;

    // a_sm: 8 rows x 256 h = 512 float4, one per thread
    ((float4*)a_sm)[tid] =
        ((const float4*)(g_PB + (size_t)base * HH))[tid];
    if (tid < HH) w2_sm[tid] = w2[tid];

    const float* __restrict__ qtb = g_QT + (size_t)b * NN;   // + h*BN + j

    float e0[4] = {0.f, 0.f, 0.f, 0.f};    // row r0,  4 j
    float e1[4] = {0.f, 0.f, 0.f, 0.f};    // row r0+1, 4 j

    // ---- q producer: each thread moves two float4 per 8h x 512j chunk ----
    const int jf  = tid & 127;
    const int hcA = tid >> 7;              // 0..3
    const float4* src0 = (const float4*)(qtb + (size_t)hcA * BN) + jf;
    const float4* src1 = (const float4*)(qtb + (size_t)(hcA + 4) * BN) + jf;

    float4 pre0 = *src0;
    float4 pre1 = *src1;
    ((float4*)q_sm)[tid]       = pre0;     // chunk 0 -> buffer 0
    ((float4*)q_sm)[tid + 512] = pre1;
    __syncthreads();

    for (int c = 0; c < 32; ++c) {
        const float* cur = q_sm + (c & 1) * (8 * NN);
        float*       nxt = q_sm + ((c + 1) & 1) * (8 * NN);

        if (c + 1 < 32) {                  // fire next chunk's global loads
            src0 += 2 * BN;                // 8 rows of BN floats, as float4s
            src1 += 2 * BN;
            pre0 = *src0;
            pre1 = *src1;
        }

        // burst-load q for this chunk into registers (8 back-to-back LDS.128)
        float4 qr[8];
#pragma unroll
        for (int hc = 0; hc < 8; ++hc)
            qr[hc] = *(const float4*)(cur + hc * NN + 4 * jq);

        const int h0 = c * 8;
        // register-cache a and w for this chunk (broadcast LDS.128)
        float av0[8], av1[8], wv[8];
        *(float4*)(av0)     = *(const float4*)(a_sm + (r0    ) * HH + h0);
        *(float4*)(av0 + 4) = *(const float4*)(a_sm + (r0    ) * HH + h0 + 4);
        *(float4*)(av1)     = *(const float4*)(a_sm + (r0 + 1) * HH + h0);
        *(float4*)(av1 + 4) = *(const float4*)(a_sm + (r0 + 1) * HH + h0 + 4);
        *(float4*)(wv)      = *(const float4*)(w2_sm + h0);
        *(float4*)(wv + 4)  = *(const float4*)(w2_sm + h0 + 4);

#pragma unroll
        for (int hc = 0; hc < 8; ++hc) {
            const float4 q4 = qr[hc];
            const float w  = wv[hc];
            const float a0 = av0[hc];
            const float a1 = av1[hc];
            e0[0] = fmaf(fmaxf(a0 + q4.x, 0.f), w, e0[0]);
            e0[1] = fmaf(fmaxf(a0 + q4.y, 0.f), w, e0[1]);
            e0[2] = fmaf(fmaxf(a0 + q4.z, 0.f), w, e0[2]);
            e0[3] = fmaf(fmaxf(a0 + q4.w, 0.f), w, e0[3]);
            e1[0] = fmaf(fmaxf(a1 + q4.x, 0.f), w, e1[0]);
            e1[1] = fmaf(fmaxf(a1 + q4.y, 0.f), w, e1[1]);
            e1[2] = fmaf(fmaxf(a1 + q4.z, 0.f), w, e1[2]);
            e1[3] = fmaf(fmaxf(a1 + q4.w, 0.f), w, e1[3]);
        }

        if (c + 1 < 32) {                  // stage next chunk (other buffer)
            ((float4*)nxt)[tid]       = pre0;
            ((float4*)nxt)[tid + 512] = pre1;
        }
        __syncthreads();                   // nxt ready; cur reusable at c+2
    }

    // ---- leaky relu + adjacency mask (int4 loads, coalesced) ----
    const float b2v = b2[0];
    const int4 m0 = *(const int4*)(adj + ((size_t)(base + r0    )) * NN + 4 * jq);
    const int4 m1 = *(const int4*)(adj + ((size_t)(base + r0 + 1)) * NN + 4 * jq);
    {
        const int mm0[4] = {m0.x, m0.y, m0.z, m0.w};
        const int mm1[4] = {m1.x, m1.y, m1.z, m1.w};
#pragma unroll
        for (int k = 0; k < 4; ++k) {
            float v0 = e0[k] + b2v;
            float v1 = e1[k] + b2v;
            v0 = (v0 > 0.f) ? v0 : NEG_SLOPE * v0;
            v1 = (v1 > 0.f) ? v1 : NEG_SLOPE * v1;
            e0[k] = (mm0[k] > 0) ? v0 : MASK_VAL;
            e1[k] = (mm1[k] > 0) ? v1 : MASK_VAL;
        }
    }

    // ---- softmax over j: shfl reduce within warp, 4-way combine in smem ---
    const int wig = (tid >> 5) & 3;        // warp index within row group
    float mr0 = fmaxf(fmaxf(e0[0], e0[1]), fmaxf(e0[2], e0[3]));
    float mr1 = fmaxf(fmaxf(e1[0], e1[1]), fmaxf(e1[2], e1[3]));
#pragma unroll
    for (int off = 16; off > 0; off >>= 1) {
        mr0 = fmaxf(mr0, __shfl_xor_sync(0xffffffffu, mr0, off));
        mr1 = fmaxf(mr1, __shfl_xor_sync(0xffffffffu, mr1, off));
    }
    if ((tid & 31) == 0) { redm[r0][wig] = mr0; redm[r0 + 1][wig] = mr1; }
    __syncthreads();
    const float mx0 = fmaxf(fmaxf(redm[r0][0], redm[r0][1]),
                            fmaxf(redm[r0][2], redm[r0][3]));
    const float mx1 = fmaxf(fmaxf(redm[r0 + 1][0], redm[r0 + 1][1]),
                            fmaxf(redm[r0 + 1][2], redm[r0 + 1][3]));

    float s0 = 0.f, s1 = 0.f;
#pragma unroll
    for (int k = 0; k < 4; ++k) {
        e0[k] = __expf(e0[k] - mx0);
        e1[k] = __expf(e1[k] - mx1);
        s0 += e0[k];
        s1 += e1[k];
    }
#pragma unroll
    for (int off = 16; off > 0; off >>= 1) {
        s0 += __shfl_xor_sync(0xffffffffu, s0, off);
        s1 += __shfl_xor_sync(0xffffffffu, s1, off);
    }
    if ((tid & 31) == 0) { reds[r0][wig] = s0; reds[r0 + 1][wig] = s1; }
    __syncthreads();
    const float inv0 = 1.0f / (reds[r0][0] + reds[r0][1] + reds[r0][2] + reds[r0][3]);
    const float inv1 = 1.0f / (reds[r0 + 1][0] + reds[r0 + 1][1] +
                               reds[r0 + 1][2] + reds[r0 + 1][3]);

    // ---- attention tile into smem (buffer 0 of q_sm; e-loop reads done) ---
    float* att = q_sm;
    *(float4*)(att + (r0    ) * NN + 4 * jq) =
        make_float4(e0[0] * inv0, e0[1] * inv0, e0[2] * inv0, e0[3] * inv0);
    *(float4*)(att + (r0 + 1) * NN + 4 * jq) =
        make_float4(e1[0] * inv1, e1[1] * inv1, e1[2] * inv1, e1[3] * inv1);
    __syncthreads();

    // attention[0,0,:] output (block 0 holds b=0, i=0 at row 0)
    if (write_att && blockIdx.x == 0)
        out[BB * NN * FF + tid] = att[tid];     // row 0 = att[0..511]

    // ---- next_h[b, it0+rw, f] = sum_j att[rw][j] * x[b, j, f] -------------
    // thread = (f-quad fq, row rw, j-half); halves combined via a_sm.
    const int fq   = tid & 31;             // f = 4*fq..4*fq+3
    const int rw   = (tid >> 5) & 7;       // row 0..7
    const int half = tid >> 8;             // 0/1 -> j in [0,256) / [256,512)
    const float* __restrict__ arow = att + rw * NN + half * 256;
    const float* __restrict__ xrow = x + (size_t)b * NN * FF
                                       + (size_t)half * 256 * FF + 4 * fq;

    float4 acc = make_float4(0.f, 0.f, 0.f, 0.f);
#pragma unroll 2
    for (int jj = 0; jj < 256; jj += 4) {
        const float4 a4 = *(const float4*)(arow + jj);            // broadcast
        const float4 x0 = *(const float4*)(xrow + (size_t)(jj + 0) * FF);
        const float4 x1 = *(const float4*)(xrow + (size_t)(jj + 1) * FF);
        const float4 x2 = *(const float4*)(xrow + (size_t)(jj + 2) * FF);
        const float4 x3 = *(const float4*)(xrow + (size_t)(jj + 3) * FF);
        acc.x = fmaf(a4.x, x0.x, acc.x);
        acc.y = fmaf(a4.x, x0.y, acc.y);
        acc.z = fmaf(a4.x, x0.z, acc.z);
        acc.w = fmaf(a4.x, x0.w, acc.w);
        acc.x = fmaf(a4.y, x1.x, acc.x);
        acc.y = fmaf(a4.y, x1.y, acc.y);
        acc.z = fmaf(a4.y, x1.z, acc.z);
        acc.w = fmaf(a4.y, x1.w, acc.w);
        acc.x = fmaf(a4.z, x2.x, acc.x);
        acc.y = fmaf(a4.z, x2.y, acc.y);
        acc.z = fmaf(a4.z, x2.z, acc.z);
        acc.w = fmaf(a4.z, x2.w, acc.w);
        acc.x = fmaf(a4.w, x3.x, acc.x);
        acc.y = fmaf(a4.w, x3.y, acc.y);
        acc.z = fmaf(a4.w, x3.z, acc.z);
        acc.w = fmaf(a4.w, x3.w, acc.w);
    }

    // combine halves through a_sm (its previous contents are dead now)
    if (half == 1)
        *(float4*)(a_sm + rw * FF + 4 * fq) = acc;
    __syncthreads();
    if (half == 0) {
        const float4 p = *(const float4*)(a_sm + rw * FF + 4 * fq);
        acc.x += p.x; acc.y += p.y; acc.z += p.z; acc.w += p.w;
        *(float4*)(out + (size_t)(base + rw) * FF + 4 * fq) = acc;
    }
}

// ---------------------------------------------------------------------------
// Launch. Input order per setup_inputs: x, w1, b1, w2, b2, adj
// Output: next_h (2*512*128 floats) then attention[0,0,:] (512 floats)
// ---------------------------------------------------------------------------
extern "C" void kernel_launch(void* const* d_in, const int* in_sizes, int n_in,
                              void* d_out, int out_size)
{
    const float* x   = (const float*)d_in[0];
    const float* w1  = (const float*)d_in[1];
    const float* b1  = (const float*)d_in[2];
    const float* w2  = (const float*)d_in[3];
    const float* b2  = (const float*)d_in[4];
    const int*   adj = (const int*)  d_in[5];
    float* out = (float*)d_out;

    const int write_att = (out_size >= BB * NN * FF + NN) ? 1 : 0;

    pq_kernel<<<BN / 4, 256>>>(x, w1, b1);
    attn_kernel<<<BB * (NN / 8), 512>>>(x, w2, b2, adj, out, write_att);
}

// round 17
// speedup vs baseline: 1.1146x; 1.1146x over previous
#include <cuda_runtime.h>

// Problem constants
#define BB 2
#define NN 512
#define FF 128
#define HH 256          // 2F
#define NEG_SLOPE 0.04f
#define MASK_VAL  (-9e15f)

#define BN (BB*NN)      // 1024 rows total

// Scratch: PB[bn][h] = p + b1 (row-major, h contiguous)
//          QT[h][bn] = q      (transposed: bn contiguous per h)
__device__ float g_PB[BN * HH];
__device__ float g_QT[HH * BN];

// ---------------------------------------------------------------------------
// Kernel 1: fused p/q projection. 128 blocks x 512 threads, 8 rows/block.
// Thread: h = tid&255, row-half rg = tid>>8 (rows rg*4 .. rg*4+3).
// ---------------------------------------------------------------------------
__global__ __launch_bounds__(512) void pq_kernel(
    const float* __restrict__ x,
    const float* __restrict__ w1,
    const float* __restrict__ b1)
{
    __shared__ float xs[8 * FF];          // 8 rows x 128
    const int tid = threadIdx.x;
    const int bn0 = blockIdx.x * 8;

    if (tid < 256)                         // 1024 floats = 256 float4
        ((float4*)xs)[tid] = ((const float4*)(x + (size_t)bn0 * FF))[tid];
    __syncthreads();

    const int h  = tid & 255;
    const int rb = (tid >> 8) * 4;         // row base 0 or 4
    const float* __restrict__ wrow = w1 + (size_t)h * (2 * FF);
    const float* __restrict__ xr   = xs + rb * FF;

    float accP[4] = {0.f, 0.f, 0.f, 0.f};
    float accQ[4] = {0.f, 0.f, 0.f, 0.f};

#pragma unroll 4
    for (int f = 0; f < FF; f += 4) {
        const float4 wp = *(const float4*)(wrow + f);        // L1-shared pair
        const float4 wq = *(const float4*)(wrow + FF + f);
#pragma unroll
        for (int r = 0; r < 4; ++r) {
            const float x0 = xr[r * FF + f + 0];             // broadcast LDS
            const float x1 = xr[r * FF + f + 1];
            const float x2 = xr[r * FF + f + 2];
            const float x3 = xr[r * FF + f + 3];
            accP[r] = fmaf(x0, wp.x, accP[r]);
            accP[r] = fmaf(x1, wp.y, accP[r]);
            accP[r] = fmaf(x2, wp.z, accP[r]);
            accP[r] = fmaf(x3, wp.w, accP[r]);
            accQ[r] = fmaf(x0, wq.x, accQ[r]);
            accQ[r] = fmaf(x1, wq.y, accQ[r]);
            accQ[r] = fmaf(x2, wq.z, accQ[r]);
            accQ[r] = fmaf(x3, wq.w, accQ[r]);
        }
    }

    const float b1h = b1[h];
#pragma unroll
    for (int r = 0; r < 4; ++r)                              // coalesced over h
        g_PB[(size_t)(bn0 + rb + r) * HH + h] = accP[r] + b1h;

    float4 qa = make_float4(accQ[0], accQ[1], accQ[2], accQ[3]);
    *(float4*)(g_QT + (size_t)h * BN + bn0 + rb) = qa;
}

// ---------------------------------------------------------------------------
// Kernel 2 (R11 structure, unchanged): e-scores + leaky + mask + softmax +
// att@x, fused. 128 blocks (b x 64 i-tiles of 8 rows), 512 threads.
// Thread tile: 4 consecutive j (jq = tid&127) x 2 rows (r0 = (tid>>7)*2).
// All smem traffic is 128-bit; q tile software-pipelined (2 syncs/chunk).
// ---------------------------------------------------------------------------
__global__ __launch_bounds__(512) void attn_kernel(
    const float* __restrict__ x,
    const float* __restrict__ w2,
    const float* __restrict__ b2,
    const int*   __restrict__ adj,
    float* __restrict__ out,
    int write_att)
{
    __shared__ float a_sm[8 * HH];     // 8 KB : PB rows (later: AV partials)
    __shared__ float q_sm[8 * NN];     // 16 KB: q chunk (later: attention tile)
    __shared__ float w2_sm[HH];        // 1 KB
    __shared__ float redm[8][4];       // per-row warp partial max
    __shared__ float reds[8][4];       // per-row warp partial sum

    const int tid = threadIdx.x;           // 0..511
    const int jq  = tid & 127;             // j quad: j = 4*jq+k
    const int rg  = tid >> 7;              // 0..3
    const int r0  = rg * 2;                // rows r0, r0+1
    const int b   = blockIdx.x >> 6;
    const int it0 = (blockIdx.x & 63) << 3;
    const int base = b * NN + it0;

    // a_sm: 8 rows x 256 h = 512 float4, one per thread
    ((float4*)a_sm)[tid] =
        ((const float4*)(g_PB + (size_t)base * HH))[tid];
    if (tid < HH) w2_sm[tid] = w2[tid];

    const float* __restrict__ qtb = g_QT + (size_t)b * NN;   // + h*BN + j

    float e0[4] = {0.f, 0.f, 0.f, 0.f};    // row r0,  4 j
    float e1[4] = {0.f, 0.f, 0.f, 0.f};    // row r0+1, 4 j

    // ---- software-pipelined Q tile staging ----
    const int jf  = tid & 127;
    const int hcA = tid >> 7;              // 0..3
    const float4* src0 = (const float4*)(qtb + (size_t)hcA * BN) + jf;
    const float4* src1 = (const float4*)(qtb + (size_t)(hcA + 4) * BN) + jf;
    float4* dst0 = (float4*)q_sm + tid;
    float4* dst1 = (float4*)q_sm + tid + 512;

    float4 pre0 = *src0;
    float4 pre1 = *src1;

    for (int c = 0; c < 32; ++c) {
        __syncthreads();                   // previous chunk fully consumed
        *dst0 = pre0;
        *dst1 = pre1;
        __syncthreads();

        if (c + 1 < 32) {                  // next chunk's loads land under compute
            src0 += 2 * BN;                // (float4 stride: 8 rows of BN floats)
            src1 += 2 * BN;
            pre0 = *src0;
            pre1 = *src1;
        }

        const int h0 = c * 8;
        // register-cache a and w for this chunk (all 128-bit, broadcast LDS)
        float av0[8], av1[8], wv[8];
        *(float4*)(av0)     = *(const float4*)(a_sm + (r0    ) * HH + h0);
        *(float4*)(av0 + 4) = *(const float4*)(a_sm + (r0    ) * HH + h0 + 4);
        *(float4*)(av1)     = *(const float4*)(a_sm + (r0 + 1) * HH + h0);
        *(float4*)(av1 + 4) = *(const float4*)(a_sm + (r0 + 1) * HH + h0 + 4);
        *(float4*)(wv)      = *(const float4*)(w2_sm + h0);
        *(float4*)(wv + 4)  = *(const float4*)(w2_sm + h0 + 4);

#pragma unroll
        for (int hc = 0; hc < 8; ++hc) {
            const float4 q4 = *(const float4*)(q_sm + hc * NN + 4 * jq);
            const float w  = wv[hc];
            const float a0 = av0[hc];
            const float a1 = av1[hc];
            e0[0] = fmaf(fmaxf(a0 + q4.x, 0.f), w, e0[0]);
            e0[1] = fmaf(fmaxf(a0 + q4.y, 0.f), w, e0[1]);
            e0[2] = fmaf(fmaxf(a0 + q4.z, 0.f), w, e0[2]);
            e0[3] = fmaf(fmaxf(a0 + q4.w, 0.f), w, e0[3]);
            e1[0] = fmaf(fmaxf(a1 + q4.x, 0.f), w, e1[0]);
            e1[1] = fmaf(fmaxf(a1 + q4.y, 0.f), w, e1[1]);
            e1[2] = fmaf(fmaxf(a1 + q4.z, 0.f), w, e1[2]);
            e1[3] = fmaf(fmaxf(a1 + q4.w, 0.f), w, e1[3]);
        }
    }

    // ---- leaky relu + adjacency mask (int4 loads, coalesced) ----
    const float b2v = b2[0];
    const int4 m0 = *(const int4*)(adj + ((size_t)(base + r0    )) * NN + 4 * jq);
    const int4 m1 = *(const int4*)(adj + ((size_t)(base + r0 + 1)) * NN + 4 * jq);
    {
        const int mm0[4] = {m0.x, m0.y, m0.z, m0.w};
        const int mm1[4] = {m1.x, m1.y, m1.z, m1.w};
#pragma unroll
        for (int k = 0; k < 4; ++k) {
            float v0 = e0[k] + b2v;
            float v1 = e1[k] + b2v;
            v0 = (v0 > 0.f) ? v0 : NEG_SLOPE * v0;
            v1 = (v1 > 0.f) ? v1 : NEG_SLOPE * v1;
            e0[k] = (mm0[k] > 0) ? v0 : MASK_VAL;
            e1[k] = (mm1[k] > 0) ? v1 : MASK_VAL;
        }
    }

    // ---- softmax over j: shfl reduce within warp, 4-way combine in smem ---
    const int wig = (tid >> 5) & 3;        // warp index within row group
    float mr0 = fmaxf(fmaxf(e0[0], e0[1]), fmaxf(e0[2], e0[3]));
    float mr1 = fmaxf(fmaxf(e1[0], e1[1]), fmaxf(e1[2], e1[3]));
#pragma unroll
    for (int off = 16; off > 0; off >>= 1) {
        mr0 = fmaxf(mr0, __shfl_xor_sync(0xffffffffu, mr0, off));
        mr1 = fmaxf(mr1, __shfl_xor_sync(0xffffffffu, mr1, off));
    }
    if ((tid & 31) == 0) { redm[r0][wig] = mr0; redm[r0 + 1][wig] = mr1; }
    __syncthreads();
    const float mx0 = fmaxf(fmaxf(redm[r0][0], redm[r0][1]),
                            fmaxf(redm[r0][2], redm[r0][3]));
    const float mx1 = fmaxf(fmaxf(redm[r0 + 1][0], redm[r0 + 1][1]),
                            fmaxf(redm[r0 + 1][2], redm[r0 + 1][3]));

    float s0 = 0.f, s1 = 0.f;
#pragma unroll
    for (int k = 0; k < 4; ++k) {
        e0[k] = __expf(e0[k] - mx0);
        e1[k] = __expf(e1[k] - mx1);
        s0 += e0[k];
        s1 += e1[k];
    }
#pragma unroll
    for (int off = 16; off > 0; off >>= 1) {
        s0 += __shfl_xor_sync(0xffffffffu, s0, off);
        s1 += __shfl_xor_sync(0xffffffffu, s1, off);
    }
    if ((tid & 31) == 0) { reds[r0][wig] = s0; reds[r0 + 1][wig] = s1; }
    __syncthreads();
    const float inv0 = 1.0f / (reds[r0][0] + reds[r0][1] + reds[r0][2] + reds[r0][3]);
    const float inv1 = 1.0f / (reds[r0 + 1][0] + reds[r0 + 1][1] +
                               reds[r0 + 1][2] + reds[r0 + 1][3]);

    // ---- attention tile into smem (reuse q_sm; all e-loop reads are done) --
    float* att = q_sm;
    *(float4*)(att + (r0    ) * NN + 4 * jq) =
        make_float4(e0[0] * inv0, e0[1] * inv0, e0[2] * inv0, e0[3] * inv0);
    *(float4*)(att + (r0 + 1) * NN + 4 * jq) =
        make_float4(e1[0] * inv1, e1[1] * inv1, e1[2] * inv1, e1[3] * inv1);
    __syncthreads();

    // attention[0,0,:] output (block 0 holds b=0, i=0 at row 0)
    if (write_att && blockIdx.x == 0)
        out[BB * NN * FF + tid] = att[tid];     // row 0 = att[0..511]

    // ---- next_h[b, it0+rw, f] = sum_j att[rw][j] * x[b, j, f] -------------
    // thread = (f-quad fq, row rw, j-half); halves combined via a_sm.
    const int fq   = tid & 31;             // f = 4*fq..4*fq+3
    const int rw   = (tid >> 5) & 7;       // row 0..7
    const int half = tid >> 8;             // 0/1 -> j in [0,256) / [256,512)
    const float* __restrict__ arow = att + rw * NN + half * 256;
    const float* __restrict__ xrow = x + (size_t)b * NN * FF
                                       + (size_t)half * 256 * FF + 4 * fq;

    float4 acc = make_float4(0.f, 0.f, 0.f, 0.f);
#pragma unroll 2
    for (int jj = 0; jj < 256; jj += 4) {
        const float4 a4 = *(const float4*)(arow + jj);            // broadcast
        const float4 x0 = *(const float4*)(xrow + (size_t)(jj + 0) * FF);
        const float4 x1 = *(const float4*)(xrow + (size_t)(jj + 1) * FF);
        const float4 x2 = *(const float4*)(xrow + (size_t)(jj + 2) * FF);
        const float4 x3 = *(const float4*)(xrow + (size_t)(jj + 3) * FF);
        acc.x = fmaf(a4.x, x0.x, acc.x);
        acc.y = fmaf(a4.x, x0.y, acc.y);
        acc.z = fmaf(a4.x, x0.z, acc.z);
        acc.w = fmaf(a4.x, x0.w, acc.w);
        acc.x = fmaf(a4.y, x1.x, acc.x);
        acc.y = fmaf(a4.y, x1.y, acc.y);
        acc.z = fmaf(a4.y, x1.z, acc.z);
        acc.w = fmaf(a4.y, x1.w, acc.w);
        acc.x = fmaf(a4.z, x2.x, acc.x);
        acc.y = fmaf(a4.z, x2.y, acc.y);
        acc.z = fmaf(a4.z, x2.z, acc.z);
        acc.w = fmaf(a4.z, x2.w, acc.w);
        acc.x = fmaf(a4.w, x3.x, acc.x);
        acc.y = fmaf(a4.w, x3.y, acc.y);
        acc.z = fmaf(a4.w, x3.z, acc.z);
        acc.w = fmaf(a4.w, x3.w, acc.w);
    }

    // combine halves through a_sm (its previous contents are dead now)
    if (half == 1)
        *(float4*)(a_sm + rw * FF + 4 * fq) = acc;
    __syncthreads();
    if (half == 0) {
        const float4 p = *(const float4*)(a_sm + rw * FF + 4 * fq);
        acc.x += p.x; acc.y += p.y; acc.z += p.z; acc.w += p.w;
        *(float4*)(out + (size_t)(base + rw) * FF + 4 * fq) = acc;
    }
}

// ---------------------------------------------------------------------------
// Launch. Input order per setup_inputs: x, w1, b1, w2, b2, adj
// Output: next_h (2*512*128 floats) then attention[0,0,:] (512 floats)
// ---------------------------------------------------------------------------
extern "C" void kernel_launch(void* const* d_in, const int* in_sizes, int n_in,
                              void* d_out, int out_size)
{
    const float* x   = (const float*)d_in[0];
    const float* w1  = (const float*)d_in[1];
    const float* b1  = (const float*)d_in[2];
    const float* w2  = (const float*)d_in[3];
    const float* b2  = (const float*)d_in[4];
    const int*   adj = (const int*)  d_in[5];
    float* out = (float*)d_out;

    const int write_att = (out_size >= BB * NN * FF + NN) ? 1 : 0;

    pq_kernel<<<BN / 8, 512>>>(x, w1, b1);
    attn_kernel<<<BB * (NN / 8), 512>>>(x, w2, b2, adj, out, write_att);
}